// round 8
// baseline (speedup 1.0000x reference)
#include <cuda_runtime.h>
#include <cstdint>

#define Bb 64
#define Tt 512
#define Ii 256
#define Hh 512
#define Mm (Bb*Tt)   // 32768 rows

#define NB 64        // sparse-gemm2 n-block width (cols per CTA)

__device__ __align__(16) float    g_W1[Hh*Ii];            // 0.5 MB
__device__ __align__(16) float    g_W2T[Hh*Hh];           // 1 MB, [k][n]
__device__ __align__(16) float    g_z1[Mm*Hh];            // 64 MB
__device__ __align__(16) float    g_y2[Mm*Hh];            // 64 MB
__device__ __align__(16) uint32_t g_bits[(Mm/32)*Hh];     // 2 MB, [m>>5][h], bit m&31
__device__ __align__(16) uint16_t g_list[(size_t)Mm*512]; // 33.5 MB
__device__ int g_cnt[Mm];

// -------- extract center tap of conv1: W1[h,i] = conv1_w[h,i,1] --------
__global__ void extract1_k(const float* __restrict__ src) {
    int i = blockIdx.x * blockDim.x + threadIdx.x;
    if (i < Hh*Ii) g_W1[i] = src[i*3 + 1];
}

// -------- transposed extract of conv2: W2T[k][n] = conv2_w[n,k,1] --------
__global__ void extract2t_k(const float* __restrict__ src) {
    __shared__ float tile[32][33];
    const int k0 = blockIdx.x * 32, n0 = blockIdx.y * 32;
    const int tx = threadIdx.x, ty = threadIdx.y;
    tile[ty][tx] = src[((size_t)(n0 + ty) * Hh + (k0 + tx)) * 3 + 1];
    __syncthreads();
    g_W2T[(size_t)(k0 + ty) * Hh + (n0 + tx)] = tile[tx][ty];
}

// ======== Scalar SGEMM (proven): C = A*B^T + bias ========
template<int K>
__device__ __forceinline__ void sgemm128(
    const float* __restrict__ A, const float* __restrict__ Bm,
    const float* __restrict__ bias, float* __restrict__ C)
{
    __shared__ float As[2][8][132];
    __shared__ float Bs[2][8][132];

    const int tid = threadIdx.x;
    const int tx  = tid & 15;
    const int ty  = tid >> 4;
    const int m0  = blockIdx.y * 128;
    const int n0  = blockIdx.x * 128;

    const int lr = tid >> 1;
    const int lc = (tid & 1) * 4;
    const float* Ap = A  + (size_t)(m0 + lr) * K + lc;
    const float* Bp = Bm + (size_t)(n0 + lr) * K + lc;

    float4 a4 = *(const float4*)Ap;
    float4 b4 = *(const float4*)Bp;
    As[0][lc+0][lr]=a4.x; As[0][lc+1][lr]=a4.y; As[0][lc+2][lr]=a4.z; As[0][lc+3][lr]=a4.w;
    Bs[0][lc+0][lr]=b4.x; Bs[0][lc+1][lr]=b4.y; Bs[0][lc+2][lr]=b4.z; Bs[0][lc+3][lr]=b4.w;
    __syncthreads();

    float acc[8][8];
    #pragma unroll
    for (int i = 0; i < 8; i++)
        #pragma unroll
        for (int j = 0; j < 8; j++) acc[i][j] = 0.f;

    int p = 0;
    for (int k0 = 8; k0 <= K; k0 += 8) {
        const bool more = (k0 < K);
        if (more) { a4 = *(const float4*)(Ap + k0); b4 = *(const float4*)(Bp + k0); }

        #pragma unroll
        for (int k = 0; k < 8; k++) {
            float ra[8], rb[8];
            *(float4*)&ra[0] = *(const float4*)&As[p][k][ty*8];
            *(float4*)&ra[4] = *(const float4*)&As[p][k][ty*8+4];
            *(float4*)&rb[0] = *(const float4*)&Bs[p][k][tx*8];
            *(float4*)&rb[4] = *(const float4*)&Bs[p][k][tx*8+4];
            #pragma unroll
            for (int i = 0; i < 8; i++)
                #pragma unroll
                for (int j = 0; j < 8; j++)
                    acc[i][j] = __fmaf_rn(ra[i], rb[j], acc[i][j]);
        }

        if (more) {
            const int q = p ^ 1;
            As[q][lc+0][lr]=a4.x; As[q][lc+1][lr]=a4.y; As[q][lc+2][lr]=a4.z; As[q][lc+3][lr]=a4.w;
            Bs[q][lc+0][lr]=b4.x; Bs[q][lc+1][lr]=b4.y; Bs[q][lc+2][lr]=b4.z; Bs[q][lc+3][lr]=b4.w;
            __syncthreads();
            p = q;
        }
    }

    #pragma unroll
    for (int i = 0; i < 8; i++) {
        const int m = m0 + ty*8 + i;
        float4 v0, v1;
        v0.x=acc[i][0]; v0.y=acc[i][1]; v0.z=acc[i][2]; v0.w=acc[i][3];
        v1.x=acc[i][4]; v1.y=acc[i][5]; v1.z=acc[i][6]; v1.w=acc[i][7];
        const int n = n0 + tx*8;
        v0.x+=bias[n+0]; v0.y+=bias[n+1]; v0.z+=bias[n+2]; v0.w+=bias[n+3];
        v1.x+=bias[n+4]; v1.y+=bias[n+5]; v1.z+=bias[n+6]; v1.w+=bias[n+7];
        float* cp = C + (size_t)m * Hh + n0 + tx*8;
        *(float4*)cp       = v0;
        *(float4*)(cp + 4) = v1;
    }
}

__global__ void __launch_bounds__(256, 2) sgemm1_k(const float* __restrict__ A,
                                                   const float* __restrict__ bias) {
    sgemm128<Ii>(A, g_W1, bias, g_z1);
}

// -------- scan1: LIF over t, emits spike BITS --------
#define SCH 32
__global__ void __launch_bounds__(64) scan1b_k(const float* __restrict__ th_p)
{
    const int idx = blockIdx.x * blockDim.x + threadIdx.x;
    const int b = idx >> 9;
    const int h = idx & 511;
    const float th = *th_p;
    const float inv = 1.0f / th;
    const float* zp = g_z1 + (size_t)b * Tt * Hh + h;
    uint32_t* bp = g_bits + (size_t)b * 16 * Hh + h;

    float cur[SCH], nxt[SCH];
    #pragma unroll
    for (int u = 0; u < SCH; u++) cur[u] = zp[(size_t)u * Hh];

    float m = 0.f;
    uint32_t word = 0;
    for (int t0 = 0; t0 < Tt; t0 += SCH) {
        if (t0 + SCH < Tt) {
            #pragma unroll
            for (int u = 0; u < SCH; u++) nxt[u] = zp[(size_t)(t0 + SCH + u) * Hh];
        }
        #pragma unroll
        for (int u = 0; u < SCH; u++) {
            m = m + cur[u];
            const float thr = __fmaf_rn(m, inv, -1.0f);
            if (thr >= 0.0f) word |= (1u << ((t0 + u) & 31));
            m = (thr > 0.0f) ? (m - th) : m;
        }
        if (((t0 + SCH) & 31) == 0) {
            bp[(size_t)((t0 + SCH - 32) >> 5) * Hh] = word;
            word = 0;
        }
        #pragma unroll
        for (int u = 0; u < SCH; u++) cur[u] = nxt[u];
    }
}

// -------- listify: per-row ascending-k index lists from bit matrix --------
__global__ void __launch_bounds__(256) listify_k()
{
    const int row  = blockIdx.x * 8 + (threadIdx.x >> 5);
    const int lane = threadIdx.x & 31;
    const int g32 = row >> 5, bitpos = row & 31;
    const uint32_t* wp = g_bits + (size_t)g32 * Hh + lane * 16;

    uint32_t mybits = 0;
    #pragma unroll
    for (int i = 0; i < 16; i++) mybits |= ((wp[i] >> bitpos) & 1u) << i;

    const int c = __popc(mybits);
    int incl = c;
    #pragma unroll
    for (int d = 1; d < 32; d <<= 1) {
        int v = __shfl_up_sync(0xFFFFFFFFu, incl, d);
        if (lane >= d) incl += v;
    }
    int off = incl - c;
    const int total = __shfl_sync(0xFFFFFFFFu, incl, 31);

    uint16_t* lst = g_list + (size_t)row * 512;
    const int kbase = lane * 16;
    uint32_t bits = mybits;
    while (bits) {
        const int i = __ffs(bits) - 1;
        bits &= bits - 1;
        lst[off++] = (uint16_t)(kbase + i);
    }
    if (lane == 0) g_cnt[row] = total;
}

// -------- sparse GEMM2 v2: smem W2T slab + double-buffered list staging --------
// y2[m, n0:n0+64] = ascending-k serial sum of slab rows (bitwise == dense FMA).
// Grid: 128 CTAs = 8 n-blocks x 16 row-chunks (2048 rows each).
// 256 thr: 16 rows in parallel (16 thr x float4 = 64 cols per row).
__global__ void __launch_bounds__(256) sgemm2s_k()
{
    extern __shared__ float dynsmem[];
    float*    slab = dynsmem;                           // [512][NB] = 128KB
    uint16_t* lsm  = (uint16_t*)(slab + 512*NB);        // [2][16][512] = 32KB
    __shared__ int csm[2][16];

    const int nb    = blockIdx.x & 7;
    const int chunk = blockIdx.x >> 3;
    const int n0    = nb * NB;

    // load W2T slab (coalesced, pure copy)
    for (int i = threadIdx.x; i < 512*NB/4; i += 256) {
        const int k = i >> 4;            // NB/4 = 16 float4 per k-row
        const int j = (i & 15) << 2;
        *(float4*)&slab[k*NB + j] = *(const float4*)&g_W2T[(size_t)k*Hh + n0 + j];
    }

    const int wid  = threadIdx.x >> 5;   // 8 warps
    const int lane = threadIdx.x & 31;
    const int sub  = lane >> 4;          // half-warp row id (0/1)
    const int nl   = lane & 15;
    const int ncol = nl * 4;
    const int rowbase = chunk * 2048;

    // stage batch 0 into buf 0
    {
        #pragma unroll
        for (int s = 0; s < 2; s++) {
            const int ri = wid*2 + s;
            const int m  = rowbase + ri;
            const int c  = g_cnt[m];
            if (lane == 0) csm[0][ri] = c;
            const uint16_t* lp = g_list + (size_t)m * 512;
            uint16_t* dp = lsm + (size_t)ri * 512;
            for (int j = lane; j < c; j += 32) dp[j] = lp[j];
        }
    }
    __syncthreads();

    for (int batch = 0; batch < 128; batch++) {
        const int buf = batch & 1;

        // stage next batch into the other buffer (overlaps compute)
        if (batch + 1 < 128) {
            const int nbase = rowbase + (batch + 1) * 16;
            #pragma unroll
            for (int s = 0; s < 2; s++) {
                const int ri = wid*2 + s;
                const int m  = nbase + ri;
                const int c  = g_cnt[m];
                if (lane == 0) csm[buf^1][ri] = c;
                const uint16_t* lp = g_list + (size_t)m * 512;
                uint16_t* dp = lsm + (size_t)((buf^1)*16 + ri) * 512;
                for (int j = lane; j < c; j += 32) dp[j] = lp[j];
            }
        }

        // compute current batch: warp wid handles rows wid*2 + sub
        {
            const int ri = wid*2 + sub;
            const int m  = rowbase + batch*16 + ri;
            const int c  = csm[buf][ri];
            const uint16_t* lp = lsm + (size_t)(buf*16 + ri) * 512;

            float4 acc = make_float4(0.f, 0.f, 0.f, 0.f);
            int j = 0;
            for (; j + 4 <= c; j += 4) {
                const ushort4 k4 = *(const ushort4*)(lp + j);
                const float4 w0 = *(const float4*)&slab[(int)k4.x*NB + ncol];
                const float4 w1 = *(const float4*)&slab[(int)k4.y*NB + ncol];
                const float4 w2 = *(const float4*)&slab[(int)k4.z*NB + ncol];
                const float4 w3 = *(const float4*)&slab[(int)k4.w*NB + ncol];
                acc.x += w0.x; acc.y += w0.y; acc.z += w0.z; acc.w += w0.w;
                acc.x += w1.x; acc.y += w1.y; acc.z += w1.z; acc.w += w1.w;
                acc.x += w2.x; acc.y += w2.y; acc.z += w2.z; acc.w += w2.w;
                acc.x += w3.x; acc.y += w3.y; acc.z += w3.z; acc.w += w3.w;
            }
            for (; j < c; j++) {
                const int k = lp[j];
                const float4 w = *(const float4*)&slab[k*NB + ncol];
                acc.x += w.x; acc.y += w.y; acc.z += w.z; acc.w += w.w;
            }
            *(float4*)&g_y2[(size_t)m * Hh + n0 + ncol] = acc;
        }
        __syncthreads();
    }
}

// -------- scan2: LIF with per-step bias in ref order --------
__global__ void __launch_bounds__(64) scan2_k(const float* __restrict__ th_p,
                                              const float* __restrict__ bias,
                                              float* __restrict__ out)
{
    const int idx = blockIdx.x * blockDim.x + threadIdx.x;
    const int b = idx >> 9;
    const int h = idx & 511;
    const float th = *th_p;
    const float bi = bias[h];
    const float inv = 1.0f / th;
    const float* yp = g_y2 + (size_t)b * Tt * Hh + h;
    float*       sp = out  + (size_t)b * Tt * Hh + h;

    float cur[SCH], nxt[SCH];
    #pragma unroll
    for (int u = 0; u < SCH; u++) cur[u] = yp[(size_t)u * Hh];

    float m = 0.f;
    for (int t0 = 0; t0 < Tt; t0 += SCH) {
        if (t0 + SCH < Tt) {
            #pragma unroll
            for (int u = 0; u < SCH; u++) nxt[u] = yp[(size_t)(t0 + SCH + u) * Hh];
        }
        #pragma unroll
        for (int u = 0; u < SCH; u++) {
            m = (m + cur[u]) + bi;                 // ((m + dot) + b) — ref order
            const float thr = __fmaf_rn(m, inv, -1.0f);
            sp[(size_t)(t0 + u) * Hh] = (thr >= 0.0f) ? 1.0f : 0.0f;
            m = (thr > 0.0f) ? (m - th) : m;
        }
        #pragma unroll
        for (int u = 0; u < SCH; u++) cur[u] = nxt[u];
    }
}

extern "C" void kernel_launch(void* const* d_in, const int* in_sizes, int n_in,
                              void* d_out, int out_size)
{
    const float* x   = (const float*)d_in[0];
    const float* c1w = (const float*)d_in[1];
    const float* c1b = (const float*)d_in[2];
    const float* c2w = (const float*)d_in[3];
    const float* c2b = (const float*)d_in[4];
    const float* th1 = (const float*)d_in[5];
    const float* th2 = (const float*)d_in[6];
    float* out = (float*)d_out;

    static const int SMEM2 = 512*NB*4 + 2*16*512*2;   // 128KB slab + 32KB lists
    cudaFuncSetAttribute(sgemm2s_k, cudaFuncAttributeMaxDynamicSharedMemorySize, SMEM2);

    extract1_k<<<(Hh*Ii + 255)/256, 256>>>(c1w);
    {
        dim3 bt(32, 32);
        dim3 gt(Hh/32, Hh/32);
        extract2t_k<<<gt, bt>>>(c2w);
    }

    dim3 g1(Hh/128, Mm/128);              // (4, 256)
    sgemm1_k<<<g1, 256>>>(x, c1b);
    scan1b_k<<<Mm/64, 64>>>(th1);
    listify_k<<<Mm/8, 256>>>();
    sgemm2s_k<<<128, 256, SMEM2>>>();
    scan2_k<<<Mm/64, 64>>>(th2, c2b, out);
}